// round 1
// baseline (speedup 1.0000x reference)
#include <cuda_runtime.h>

// Quantized BasicBlock:
//   a1 = act_quant(x);  y1 = conv3x3(a1, wq1); b1 = BN(y1)
//   a2 = act_quant(b1); y2 = conv3x3(a2, wq2); out = BN(y2) + x
//
// Exact-integer formulation: a = k/15 (k in 0..15 u8), wq = m*alpha/7 (m in -7..7 s8)
// conv = (alpha/105) * sum(k*m)  -> int32 exact via dp4a; scale folded into BN affine.

#define CC   128
#define C4   32
#define HH   56
#define NB   64
#define HP   58          // padded height (1-px halo each side)
#define WPAD 60          // padded row stride in words (for 16B-aligned vector loads)
#define HW   (HH*HH)     // 3136
#define NPX  (NB*HW)     // 200704 pixels per channel

// ---------------- device scratch (zero-initialized at module load) ----------------
__device__ unsigned g_alphaBits[2];
__device__ double   g_red[2][2][CC];              // [conv][sum|sumsq][c]
__device__ float    g_coef[2][2][CC];             // [conv][A|B][c]
__device__ int      g_wp[2][C4*9*CC];             // packed weights: [(ci4*9+tap)*128 + oc]
__device__ unsigned g_act[(size_t)NB*C4*HP*WPAD]; // packed padded activations (halo never written => stays 0)
__device__ float    g_y[(size_t)NB*CC*HW];        // conv output: raw integer S as float (exact)

// ---------------- zero per-launch state ----------------
__global__ void k_zero() {
    int t = blockIdx.x * blockDim.x + threadIdx.x;
    if (t < 2)   g_alphaBits[t] = 0u;
    if (t < 512) ((double*)g_red)[t] = 0.0;
}

// ---------------- alpha = max |w| ----------------
__global__ void k_alpha(const float* __restrict__ w1, const float* __restrict__ w2) {
    const float* w = blockIdx.y ? w2 : w1;
    const int n = CC * CC * 9;
    float m = 0.f;
    for (int i = blockIdx.x * blockDim.x + threadIdx.x; i < n; i += gridDim.x * blockDim.x)
        m = fmaxf(m, fabsf(w[i]));
    #pragma unroll
    for (int o = 16; o; o >>= 1) m = fmaxf(m, __shfl_xor_sync(~0u, m, o));
    __shared__ float sm[32];
    if ((threadIdx.x & 31) == 0) sm[threadIdx.x >> 5] = m;
    __syncthreads();
    if (threadIdx.x < 32) {
        m = (threadIdx.x < (blockDim.x >> 5)) ? sm[threadIdx.x] : 0.f;
        #pragma unroll
        for (int o = 16; o; o >>= 1) m = fmaxf(m, __shfl_xor_sync(~0u, m, o));
        if (threadIdx.x == 0) atomicMax(&g_alphaBits[blockIdx.y], __float_as_uint(m));
    }
}

// ---------------- quantize + pack weights ----------------
// w is OIHW [oc][ci][3][3]; pack 4 ci per int32, layout [(ci4*9+tap)*128 + oc]
__global__ void k_wq(const float* __restrict__ w1, const float* __restrict__ w2) {
    int conv = blockIdx.y;
    const float* w = conv ? w2 : w1;
    float alpha = __uint_as_float(g_alphaBits[conv]);
    int idx = blockIdx.x * blockDim.x + threadIdx.x;
    if (idx >= C4 * 9 * CC) return;
    int oc = idx & 127;
    int ci4tap = idx >> 7;       // = ci4*9 + tap
    int tap = ci4tap % 9;
    int ci4 = ci4tap / 9;
    unsigned word = 0;
    #pragma unroll
    for (int i = 0; i < 4; i++) {
        float v  = w[((size_t)oc * CC + (ci4 * 4 + i)) * 9 + tap];
        float wc = fminf(fmaxf(v / alpha, -1.f), 1.f);
        int m = __float2int_rn(wc * 7.f);      // round-nearest-even == jnp.round
        word |= (unsigned)(m & 0xff) << (8 * i);
    }
    g_wp[conv][idx] = (int)word;
}

// ---------------- quantize input x -> packed padded u8 ----------------
__global__ void k_quantA(const float* __restrict__ x) {
    int idx = blockIdx.x * blockDim.x + threadIdx.x;     // (n*C4 + c4)*HW + px
    if (idx >= NB * C4 * HW) return;
    int px  = idx % HW;
    int nc4 = idx / HW;
    int c4 = nc4 & 31, n = nc4 >> 5;
    int yy = px / HH, xx = px % HH;
    const float* xp = x + ((size_t)(n * CC + c4 * 4)) * HW + px;
    unsigned word = 0;
    #pragma unroll
    for (int i = 0; i < 4; i++) {
        float v  = xp[(size_t)i * HW];
        float xc = fminf(fmaxf(v, 0.f), 1.f);
        int k = __float2int_rn(xc * 15.f);
        word |= (unsigned)k << (8 * i);
    }
    g_act[((size_t)(n * C4 + c4) * HP + (yy + 1)) * WPAD + (xx + 1)] = word;
}

// ---------------- BN(y1) + act_quant -> packed padded u8 ----------------
__global__ void k_bnquant() {
    int idx = blockIdx.x * blockDim.x + threadIdx.x;
    if (idx >= NB * C4 * HW) return;
    int px  = idx % HW;
    int nc4 = idx / HW;
    int c4 = nc4 & 31, n = nc4 >> 5;
    int yy = px / HH, xx = px % HH;
    const float* yp = g_y + ((size_t)(n * CC + c4 * 4)) * HW + px;
    unsigned word = 0;
    #pragma unroll
    for (int i = 0; i < 4; i++) {
        int c = c4 * 4 + i;
        float v  = yp[(size_t)i * HW];
        float bn = fmaf(g_coef[0][0][c], v, g_coef[0][1][c]);
        float xc = fminf(fmaxf(bn, 0.f), 1.f);
        int k = __float2int_rn(xc * 15.f);
        word |= (unsigned)k << (8 * i);
    }
    g_act[((size_t)(n * C4 + c4) * HP + (yy + 1)) * WPAD + (xx + 1)] = word;
}

// ---------------- dp4a conv: 32 oc x (4 rows x 56 cols) per block ----------------
// grid (14 rowtiles, 4 ocblocks, 64 n), block 448 = 8 oc-quads x 56 px-groups(4px)
__global__ void __launch_bounds__(448) k_conv(int conv) {
    const int* __restrict__ Wg = g_wp[conv];
    __shared__ int Ws[C4 * 9 * 32];                 // 36864 B
    int tid = threadIdx.x;
    int rt = blockIdx.x, ocb = blockIdx.y, n = blockIdx.z;

    for (int i = tid; i < C4 * 9 * 32; i += 448)
        Ws[i] = Wg[(i >> 5) * CC + ocb * 32 + (i & 31)];
    __syncthreads();

    int q   = tid & 7;          // oc quad (4 oc)
    int pxg = tid >> 3;         // 0..55
    int r   = pxg / 14;
    int cg  = pxg % 14;
    int oy  = rt * 4 + r;
    int ox0 = cg * 4;

    int acc[4][4];
    #pragma unroll
    for (int i = 0; i < 4; i++)
        #pragma unroll
        for (int j = 0; j < 4; j++) acc[i][j] = 0;

    const unsigned* Abase = g_act + ((size_t)(n * C4) * HP + oy) * WPAD + ox0;

    for (int ci4 = 0; ci4 < C4; ci4++) {
        const unsigned* ap = Abase + (size_t)ci4 * HP * WPAD;
        const int4* wr = (const int4*)&Ws[ci4 * 9 * 32 + q * 4];
        #pragma unroll
        for (int dy = 0; dy < 3; dy++) {
            const unsigned* aprow = ap + dy * WPAD;
            uint4 a03 = *(const uint4*)aprow;          // 16B-aligned (ox0 mult of 4, WPAD mult of 4)
            uint2 a45 = *(const uint2*)(aprow + 4);
            unsigned a[6] = {a03.x, a03.y, a03.z, a03.w, a45.x, a45.y};
            #pragma unroll
            for (int dx = 0; dx < 3; dx++) {
                int4 w = wr[(dy * 3 + dx) * 8];        // tap stride = 32 ints = 8 int4
                #pragma unroll
                for (int j = 0; j < 4; j++) {
                    int av = (int)a[dx + j];           // bytes 0..15: signed == unsigned
                    acc[0][j] = __dp4a(av, w.x, acc[0][j]);
                    acc[1][j] = __dp4a(av, w.y, acc[1][j]);
                    acc[2][j] = __dp4a(av, w.z, acc[2][j]);
                    acc[3][j] = __dp4a(av, w.w, acc[3][j]);
                }
            }
        }
    }

    size_t obase = ((size_t)(n * CC + ocb * 32 + q * 4)) * HW + oy * HH + ox0;
    #pragma unroll
    for (int i = 0; i < 4; i++) {
        float4 v = make_float4((float)acc[i][0], (float)acc[i][1],
                               (float)acc[i][2], (float)acc[i][3]);
        *(float4*)(g_y + obase + (size_t)i * HW) = v;   // exact: |S| << 2^24
    }
}

// ---------------- per-channel sum / sumsq of S (double) ----------------
__global__ void k_reduce(int slot) {
    int c = blockIdx.x, seg = blockIdx.y;    // 16 segs x 4 images
    double s = 0.0, s2 = 0.0;
    for (int n = seg * 4; n < seg * 4 + 4; n++) {
        const float* yp = g_y + ((size_t)(n * CC + c)) * HW;
        for (int i = threadIdx.x; i < HW; i += blockDim.x) {
            double v = yp[i];
            s += v; s2 += v * v;
        }
    }
    #pragma unroll
    for (int o = 16; o; o >>= 1) {
        s  += __shfl_xor_sync(~0u, s,  o);
        s2 += __shfl_xor_sync(~0u, s2, o);
    }
    __shared__ double sm[2][8];
    int w = threadIdx.x >> 5;
    if ((threadIdx.x & 31) == 0) { sm[0][w] = s; sm[1][w] = s2; }
    __syncthreads();
    if (threadIdx.x == 0) {
        for (int i = 1; i < (int)(blockDim.x >> 5); i++) { s += sm[0][i]; s2 += sm[1][i]; }
        atomicAdd(&g_red[slot][0][c], s);
        atomicAdd(&g_red[slot][1][c], s2);
    }
}

// ---------------- BN coefficients: bn(y) = A*S + B with y = S*scale ----------------
__global__ void k_stats(int slot, const float* __restrict__ gamma, const float* __restrict__ beta) {
    int c = threadIdx.x;
    double scale = (double)__uint_as_float(g_alphaBits[slot]) / 105.0;  // alpha/(15*7)
    double np = (double)NPX;
    double mean = g_red[slot][0][c] / np;
    double var  = g_red[slot][1][c] / np - mean * mean;
    double meanY = mean * scale;
    double varY  = var * scale * scale;
    double rstd  = 1.0 / sqrt(varY + 1e-5);
    double g = (double)gamma[c];
    g_coef[slot][0][c] = (float)(g * rstd * scale);
    g_coef[slot][1][c] = (float)((double)beta[c] - g * rstd * meanY);
}

// ---------------- out = A2*S2 + B2 + x ----------------
__global__ void k_final(const float* __restrict__ x, float* __restrict__ out) {
    int idx = blockIdx.x * blockDim.x + threadIdx.x;      // float4 index
    const int total4 = NB * CC * HW / 4;
    if (idx >= total4) return;
    int e = idx * 4;
    int c = (e / HW) % CC;                                 // HW % 4 == 0: no plane crossing
    float A = g_coef[1][0][c], B = g_coef[1][1][c];
    float4 yv = ((const float4*)g_y)[idx];
    float4 xv = ((const float4*)x)[idx];
    float4 o;
    o.x = fmaf(A, yv.x, B) + xv.x;
    o.y = fmaf(A, yv.y, B) + xv.y;
    o.z = fmaf(A, yv.z, B) + xv.z;
    o.w = fmaf(A, yv.w, B) + xv.w;
    ((float4*)out)[idx] = o;
}

// ---------------- launcher ----------------
extern "C" void kernel_launch(void* const* d_in, const int* in_sizes, int n_in,
                              void* d_out, int out_size) {
    const float* x      = (const float*)d_in[0];
    const float* w1     = (const float*)d_in[1];
    const float* w2     = (const float*)d_in[2];
    const float* gamma1 = (const float*)d_in[3];
    const float* beta1  = (const float*)d_in[4];
    const float* gamma2 = (const float*)d_in[5];
    const float* beta2  = (const float*)d_in[6];
    float* out = (float*)d_out;

    k_zero<<<2, 256>>>();
    k_alpha<<<dim3(32, 2), 256>>>(w1, w2);
    k_wq<<<dim3((C4 * 9 * CC + 255) / 256, 2), 256>>>(w1, w2);

    const int nElemBlocks = (NB * C4 * HW + 255) / 256;
    k_quantA<<<nElemBlocks, 256>>>(x);

    dim3 cgrid(14, 4, NB);
    k_conv<<<cgrid, 448>>>(0);
    k_reduce<<<dim3(CC, 16), 256>>>(0);
    k_stats<<<1, CC>>>(0, gamma1, beta1);

    k_bnquant<<<nElemBlocks, 256>>>();
    k_conv<<<cgrid, 448>>>(1);
    k_reduce<<<dim3(CC, 16), 256>>>(1);
    k_stats<<<1, CC>>>(1, gamma2, beta2);

    const int total4 = NB * CC * HW / 4;
    k_final<<<(total4 + 255) / 256, 256>>>(x, out);
}

// round 2
// speedup vs baseline: 1.0006x; 1.0006x over previous
#include <cuda_runtime.h>

// Quantized BasicBlock:
//   a1 = act_quant(x);  y1 = conv3x3(a1, wq1); b1 = BN(y1)
//   a2 = act_quant(b1); y2 = conv3x3(a2, wq2); out = BN(y2) + x
//
// Exact-integer formulation: a = k/15 (k in 0..15 u8), wq = m*alpha/7 (m in -7..7 s8)
// conv = (alpha/105) * sum(k*m)  -> int32 exact via dp4a; scale folded into BN affine.

#define CC   128
#define C4   32
#define HH   56
#define NB   64
#define HP   58          // padded height (1-px halo each side)
#define WPAD 60          // padded row stride in words (for 16B-aligned vector loads)
#define HW   (HH*HH)     // 3136
#define NPX  (NB*HW)     // 200704 pixels per channel

// ---------------- device scratch (zero-initialized at module load) ----------------
__device__ unsigned g_alphaBits[2];
__device__ double   g_red[2][2][CC];              // [conv][sum|sumsq][c]
__device__ float    g_coef[2][2][CC];             // [conv][A|B][c]
__device__ int      g_wp[2][C4*9*CC];             // packed weights: [(ci4*9+tap)*128 + oc]
__device__ unsigned g_act[(size_t)NB*C4*HP*WPAD]; // packed padded activations (halo never written => stays 0)
__device__ float    g_y[(size_t)NB*CC*HW];        // conv output: raw integer S as float (exact)

// ---------------- zero per-launch state ----------------
__global__ void k_zero() {
    int t = blockIdx.x * blockDim.x + threadIdx.x;
    if (t < 2)   g_alphaBits[t] = 0u;
    if (t < 512) ((double*)g_red)[t] = 0.0;
}

// ---------------- alpha = max |w| ----------------
__global__ void k_alpha(const float* __restrict__ w1, const float* __restrict__ w2) {
    const float* w = blockIdx.y ? w2 : w1;
    const int n = CC * CC * 9;
    float m = 0.f;
    for (int i = blockIdx.x * blockDim.x + threadIdx.x; i < n; i += gridDim.x * blockDim.x)
        m = fmaxf(m, fabsf(w[i]));
    #pragma unroll
    for (int o = 16; o; o >>= 1) m = fmaxf(m, __shfl_xor_sync(~0u, m, o));
    __shared__ float sm[32];
    if ((threadIdx.x & 31) == 0) sm[threadIdx.x >> 5] = m;
    __syncthreads();
    if (threadIdx.x < 32) {
        m = (threadIdx.x < (blockDim.x >> 5)) ? sm[threadIdx.x] : 0.f;
        #pragma unroll
        for (int o = 16; o; o >>= 1) m = fmaxf(m, __shfl_xor_sync(~0u, m, o));
        if (threadIdx.x == 0) atomicMax(&g_alphaBits[blockIdx.y], __float_as_uint(m));
    }
}

// ---------------- quantize + pack weights ----------------
// w is OIHW [oc][ci][3][3]; pack 4 ci per int32, layout [(ci4*9+tap)*128 + oc]
__global__ void k_wq(const float* __restrict__ w1, const float* __restrict__ w2) {
    int conv = blockIdx.y;
    const float* w = conv ? w2 : w1;
    float alpha = __uint_as_float(g_alphaBits[conv]);
    int idx = blockIdx.x * blockDim.x + threadIdx.x;
    if (idx >= C4 * 9 * CC) return;
    int oc = idx & 127;
    int ci4tap = idx >> 7;       // = ci4*9 + tap
    int tap = ci4tap % 9;
    int ci4 = ci4tap / 9;
    unsigned word = 0;
    #pragma unroll
    for (int i = 0; i < 4; i++) {
        float v  = w[((size_t)oc * CC + (ci4 * 4 + i)) * 9 + tap];
        float wc = fminf(fmaxf(v / alpha, -1.f), 1.f);
        int m = __float2int_rn(wc * 7.f);      // round-nearest-even == jnp.round
        word |= (unsigned)(m & 0xff) << (8 * i);
    }
    g_wp[conv][idx] = (int)word;
}

// ---------------- quantize input x -> packed padded u8 ----------------
__global__ void k_quantA(const float* __restrict__ x) {
    int idx = blockIdx.x * blockDim.x + threadIdx.x;     // (n*C4 + c4)*HW + px
    if (idx >= NB * C4 * HW) return;
    int px  = idx % HW;
    int nc4 = idx / HW;
    int c4 = nc4 & 31, n = nc4 >> 5;
    int yy = px / HH, xx = px % HH;
    const float* xp = x + ((size_t)(n * CC + c4 * 4)) * HW + px;
    unsigned word = 0;
    #pragma unroll
    for (int i = 0; i < 4; i++) {
        float v  = xp[(size_t)i * HW];
        float xc = fminf(fmaxf(v, 0.f), 1.f);
        int k = __float2int_rn(xc * 15.f);
        word |= (unsigned)k << (8 * i);
    }
    g_act[((size_t)(n * C4 + c4) * HP + (yy + 1)) * WPAD + (xx + 1)] = word;
}

// ---------------- BN(y1) + act_quant -> packed padded u8 ----------------
__global__ void k_bnquant() {
    int idx = blockIdx.x * blockDim.x + threadIdx.x;
    if (idx >= NB * C4 * HW) return;
    int px  = idx % HW;
    int nc4 = idx / HW;
    int c4 = nc4 & 31, n = nc4 >> 5;
    int yy = px / HH, xx = px % HH;
    const float* yp = g_y + ((size_t)(n * CC + c4 * 4)) * HW + px;
    unsigned word = 0;
    #pragma unroll
    for (int i = 0; i < 4; i++) {
        int c = c4 * 4 + i;
        float v  = yp[(size_t)i * HW];
        float bn = fmaf(g_coef[0][0][c], v, g_coef[0][1][c]);
        float xc = fminf(fmaxf(bn, 0.f), 1.f);
        int k = __float2int_rn(xc * 15.f);
        word |= (unsigned)k << (8 * i);
    }
    g_act[((size_t)(n * C4 + c4) * HP + (yy + 1)) * WPAD + (xx + 1)] = word;
}

// ---------------- dp4a conv: 32 oc x (4 rows x 56 cols) per block ----------------
// grid (14 rowtiles, 4 ocblocks, 64 n), block 448 = 8 oc-quads x 56 px-groups(4px)
__global__ void __launch_bounds__(448) k_conv(int conv) {
    const int* __restrict__ Wg = g_wp[conv];
    __shared__ int Ws[C4 * 9 * 32];                 // 36864 B
    int tid = threadIdx.x;
    int rt = blockIdx.x, ocb = blockIdx.y, n = blockIdx.z;

    for (int i = tid; i < C4 * 9 * 32; i += 448)
        Ws[i] = Wg[(i >> 5) * CC + ocb * 32 + (i & 31)];
    __syncthreads();

    int q   = tid & 7;          // oc quad (4 oc)
    int pxg = tid >> 3;         // 0..55
    int r   = pxg / 14;
    int cg  = pxg % 14;
    int oy  = rt * 4 + r;
    int ox0 = cg * 4;

    int acc[4][4];
    #pragma unroll
    for (int i = 0; i < 4; i++)
        #pragma unroll
        for (int j = 0; j < 4; j++) acc[i][j] = 0;

    const unsigned* Abase = g_act + ((size_t)(n * C4) * HP + oy) * WPAD + ox0;

    for (int ci4 = 0; ci4 < C4; ci4++) {
        const unsigned* ap = Abase + (size_t)ci4 * HP * WPAD;
        const int4* wr = (const int4*)&Ws[ci4 * 9 * 32 + q * 4];
        #pragma unroll
        for (int dy = 0; dy < 3; dy++) {
            const unsigned* aprow = ap + dy * WPAD;
            uint4 a03 = *(const uint4*)aprow;          // 16B-aligned (ox0 mult of 4, WPAD mult of 4)
            uint2 a45 = *(const uint2*)(aprow + 4);
            unsigned a[6] = {a03.x, a03.y, a03.z, a03.w, a45.x, a45.y};
            #pragma unroll
            for (int dx = 0; dx < 3; dx++) {
                int4 w = wr[(dy * 3 + dx) * 8];        // tap stride = 32 ints = 8 int4
                #pragma unroll
                for (int j = 0; j < 4; j++) {
                    int av = (int)a[dx + j];           // bytes 0..15: signed == unsigned
                    acc[0][j] = __dp4a(av, w.x, acc[0][j]);
                    acc[1][j] = __dp4a(av, w.y, acc[1][j]);
                    acc[2][j] = __dp4a(av, w.z, acc[2][j]);
                    acc[3][j] = __dp4a(av, w.w, acc[3][j]);
                }
            }
        }
    }

    size_t obase = ((size_t)(n * CC + ocb * 32 + q * 4)) * HW + oy * HH + ox0;
    #pragma unroll
    for (int i = 0; i < 4; i++) {
        float4 v = make_float4((float)acc[i][0], (float)acc[i][1],
                               (float)acc[i][2], (float)acc[i][3]);
        *(float4*)(g_y + obase + (size_t)i * HW) = v;   // exact: |S| << 2^24
    }
}

// ---------------- per-channel sum / sumsq of S (double) ----------------
__global__ void k_reduce(int slot) {
    int c = blockIdx.x, seg = blockIdx.y;    // 16 segs x 4 images
    double s = 0.0, s2 = 0.0;
    for (int n = seg * 4; n < seg * 4 + 4; n++) {
        const float* yp = g_y + ((size_t)(n * CC + c)) * HW;
        for (int i = threadIdx.x; i < HW; i += blockDim.x) {
            double v = yp[i];
            s += v; s2 += v * v;
        }
    }
    #pragma unroll
    for (int o = 16; o; o >>= 1) {
        s  += __shfl_xor_sync(~0u, s,  o);
        s2 += __shfl_xor_sync(~0u, s2, o);
    }
    __shared__ double sm[2][8];
    int w = threadIdx.x >> 5;
    if ((threadIdx.x & 31) == 0) { sm[0][w] = s; sm[1][w] = s2; }
    __syncthreads();
    if (threadIdx.x == 0) {
        for (int i = 1; i < (int)(blockDim.x >> 5); i++) { s += sm[0][i]; s2 += sm[1][i]; }
        atomicAdd(&g_red[slot][0][c], s);
        atomicAdd(&g_red[slot][1][c], s2);
    }
}

// ---------------- BN coefficients: bn(y) = A*S + B with y = S*scale ----------------
__global__ void k_stats(int slot, const float* __restrict__ gamma, const float* __restrict__ beta) {
    int c = threadIdx.x;
    double scale = (double)__uint_as_float(g_alphaBits[slot]) / 105.0;  // alpha/(15*7)
    double np = (double)NPX;
    double mean = g_red[slot][0][c] / np;
    double var  = g_red[slot][1][c] / np - mean * mean;
    double meanY = mean * scale;
    double varY  = var * scale * scale;
    double rstd  = 1.0 / sqrt(varY + 1e-5);
    double g = (double)gamma[c];
    g_coef[slot][0][c] = (float)(g * rstd * scale);
    g_coef[slot][1][c] = (float)((double)beta[c] - g * rstd * meanY);
}

// ---------------- out = A2*S2 + B2 + x ----------------
__global__ void k_final(const float* __restrict__ x, float* __restrict__ out) {
    int idx = blockIdx.x * blockDim.x + threadIdx.x;      // float4 index
    const int total4 = NB * CC * HW / 4;
    if (idx >= total4) return;
    int e = idx * 4;
    int c = (e / HW) % CC;                                 // HW % 4 == 0: no plane crossing
    float A = g_coef[1][0][c], B = g_coef[1][1][c];
    float4 yv = ((const float4*)g_y)[idx];
    float4 xv = ((const float4*)x)[idx];
    float4 o;
    o.x = fmaf(A, yv.x, B) + xv.x;
    o.y = fmaf(A, yv.y, B) + xv.y;
    o.z = fmaf(A, yv.z, B) + xv.z;
    o.w = fmaf(A, yv.w, B) + xv.w;
    ((float4*)out)[idx] = o;
}

// ---------------- launcher ----------------
extern "C" void kernel_launch(void* const* d_in, const int* in_sizes, int n_in,
                              void* d_out, int out_size) {
    const float* x      = (const float*)d_in[0];
    const float* w1     = (const float*)d_in[1];
    const float* w2     = (const float*)d_in[2];
    const float* gamma1 = (const float*)d_in[3];
    const float* beta1  = (const float*)d_in[4];
    const float* gamma2 = (const float*)d_in[5];
    const float* beta2  = (const float*)d_in[6];
    float* out = (float*)d_out;

    k_zero<<<2, 256>>>();
    k_alpha<<<dim3(32, 2), 256>>>(w1, w2);
    k_wq<<<dim3((C4 * 9 * CC + 255) / 256, 2), 256>>>(w1, w2);

    const int nElemBlocks = (NB * C4 * HW + 255) / 256;
    k_quantA<<<nElemBlocks, 256>>>(x);

    dim3 cgrid(14, 4, NB);
    k_conv<<<cgrid, 448>>>(0);
    k_reduce<<<dim3(CC, 16), 256>>>(0);
    k_stats<<<1, CC>>>(0, gamma1, beta1);

    k_bnquant<<<nElemBlocks, 256>>>();
    k_conv<<<cgrid, 448>>>(1);
    k_reduce<<<dim3(CC, 16), 256>>>(1);
    k_stats<<<1, CC>>>(1, gamma2, beta2);

    const int total4 = NB * CC * HW / 4;
    k_final<<<(total4 + 255) / 256, 256>>>(x, out);
}